// round 4
// baseline (speedup 1.0000x reference)
#include <cuda_runtime.h>

// SplineLoss on GB300: reference samples the spline only at integer knot
// times (t = 0,10,...,1020) where dx == 0.0 exactly, so all moment terms
// vanish: loss == mean over s,b,d of (true[b,10s,d]-pred[b,10s,d])^2.
//
// R4: cycle-count minimization (kernel runs at unramped DVFS clock, so wall
// time tracks critical-path cycles):
//  - 208 blocks (2 per sample time) -> all 148 SMs issue loads
//  - acq_rel ticket atomic instead of 2x threadfence (MEMBAR.GPU)
//  - last block reads 208 partials with MLP=7 (one L2 latency)

#define T_ 1024
#define D4_ 16                   // 64 floats per row = 16 float4
#define S_ 103                   // sample times 0,10,...,1020
#define ROW_STRIDE4_ (T_ * D4_)  // float4 stride between batches
#define COUNT_ 843776.0f         // 128 * 103 * 64

constexpr int NBLK = 2 * S_;     // 206... use 2 blocks per s
constexpr int NTHR = 256;

__device__ float g_partials[NBLK];
__device__ unsigned int g_ticket = 0;   // reset by last block each call

__global__ __launch_bounds__(NTHR) void spline_mse_r4(
    const float* __restrict__ yt, const float* __restrict__ yp,
    float* __restrict__ out)
{
    const int s    = blockIdx.x >> 1;          // 0..102
    const int half = blockIdx.x & 1;           // batches [half*64, half*64+64)
    const int base = s * 10 * D4_ + half * 64 * ROW_STRIDE4_;
    const float4* __restrict__ a4 = (const float4*)yt + base;
    const float4* __restrict__ b4 = (const float4*)yp + base;

    const int d4   = threadIdx.x & (D4_ - 1);
    const int brel = threadIdx.x >> 4;         // 0..15, step 16 -> 64 batches

    // 8 independent LDG.128, front-batched (MLP=8 per thread)
    float4 va[4], vb[4];
    #pragma unroll
    for (int k = 0; k < 4; k++) {
        int addr = (brel + k * 16) * ROW_STRIDE4_ + d4;
        va[k] = __ldg(&a4[addr]);
        vb[k] = __ldg(&b4[addr]);
    }

    float acc = 0.0f;
    #pragma unroll
    for (int k = 0; k < 4; k++) {
        float e0 = va[k].x - vb[k].x;
        float e1 = va[k].y - vb[k].y;
        float e2 = va[k].z - vb[k].z;
        float e3 = va[k].w - vb[k].w;
        acc = fmaf(e0, e0, acc);
        acc = fmaf(e1, e1, acc);
        acc = fmaf(e2, e2, acc);
        acc = fmaf(e3, e3, acc);
    }

    // block reduce (fixed order -> deterministic)
    #pragma unroll
    for (int o = 16; o > 0; o >>= 1)
        acc += __shfl_down_sync(0xffffffffu, acc, o);

    __shared__ float sh[NTHR / 32];
    if ((threadIdx.x & 31) == 0) sh[threadIdx.x >> 5] = acc;
    __syncthreads();

    if (threadIdx.x >= 32) return;             // warp 0 only from here

    float v = (threadIdx.x < NTHR / 32) ? sh[threadIdx.x] : 0.0f;
    #pragma unroll
    for (int o = 4; o > 0; o >>= 1)            // 8 lanes carry data
        v += __shfl_down_sync(0xffffffffu, v, o);

    // publish partial (st.cg) + acq_rel ticket: release makes our STG
    // visible, acquire on the last ticket makes ALL partials visible.
    unsigned int ticket = 0;
    if (threadIdx.x == 0) {
        asm volatile("st.global.cg.f32 [%0], %1;"
                     :: "l"(&g_partials[blockIdx.x]), "f"(v) : "memory");
        asm volatile("atom.acq_rel.gpu.global.add.u32 %0, [%1], 1;"
                     : "=r"(ticket) : "l"(&g_ticket) : "memory");
    }
    ticket = __shfl_sync(0xffffffffu, ticket, 0);
    if (ticket != NBLK - 1) return;            // not the last block

    // last block: read 208 partials, MLP ~7 per lane, fixed order
    float tot = 0.0f;
    #pragma unroll
    for (int k = 0; k < (NBLK + 31) / 32; k++) {
        int idx = k * 32 + threadIdx.x;
        if (idx < NBLK) {
            float p;
            asm volatile("ld.global.cg.f32 %0, [%1];"
                         : "=f"(p) : "l"(&g_partials[idx]));
            tot += p;
        }
    }
    #pragma unroll
    for (int o = 16; o > 0; o >>= 1)
        tot += __shfl_down_sync(0xffffffffu, tot, o);

    if (threadIdx.x == 0) {
        out[0] = tot / COUNT_;
        g_ticket = 0;                          // reset for next replay
    }
}

extern "C" void kernel_launch(void* const* d_in, const int* in_sizes, int n_in,
                              void* d_out, int out_size)
{
    const float* yt = (const float*)d_in[0];   // true_frames
    const float* yp = (const float*)d_in[1];   // predicted_frames
    spline_mse_r4<<<NBLK, NTHR>>>(yt, yp, (float*)d_out);
}

// round 5
// speedup vs baseline: 1.2930x; 1.2930x over previous
#include <cuda_runtime.h>

// SplineLoss on GB300: reference samples the spline only at integer knot
// times (t = 0,10,...,1020) where dx == 0.0 exactly, so all moment terms
// vanish: loss == mean over s,b,d of (true[b,10s,d]-pred[b,10s,d])^2.
//
// R5:
//  - 412 blocks x 256 thr (~22 warps/SM): enough outstanding LDGs to be
//    DRAM-throughput-bound instead of latency-bound (R4: occ 11.7%, 940GB/s)
//  - single fused atomic tail: partial -> fixed-point u64, one
//    atomicAdd((fixed<<16)|1). Deterministic (integer add is exact &
//    commutative); returned old value gives the last block the full sum.
//    No partials array, no fence, no second global read.

#define T_ 1024
#define D4_ 16                   // 64 floats per row = 16 float4
#define S_ 103                   // sample times 0,10,...,1020
#define ROW_STRIDE4_ (T_ * D4_)  // float4 stride between batches
#define COUNT_ 843776.0          // 128 * 103 * 64
#define FIX_SCALE 16777216.0     // 2^24

constexpr int NBLK = 4 * S_;     // 412: 4 blocks per sample time
constexpr int NTHR = 256;

__device__ unsigned long long g_acc = 0;   // [63:16] fixed sum, [15:0] count

__global__ __launch_bounds__(NTHR) void spline_mse_r5(
    const float* __restrict__ yt, const float* __restrict__ yp,
    float* __restrict__ out)
{
    const int s       = blockIdx.x >> 2;       // 0..102
    const int quarter = blockIdx.x & 3;        // batches [q*32, q*32+32)
    const int base = s * 10 * D4_ + quarter * 32 * ROW_STRIDE4_;
    const float4* __restrict__ a4 = (const float4*)yt + base;
    const float4* __restrict__ b4 = (const float4*)yp + base;

    const int d4   = threadIdx.x & (D4_ - 1);
    const int brel = threadIdx.x >> 4;         // 0..15, +16 -> 32 batches

    // 4 independent LDG.128 per thread, front-batched
    float4 va[2], vb[2];
    #pragma unroll
    for (int k = 0; k < 2; k++) {
        int addr = (brel + k * 16) * ROW_STRIDE4_ + d4;
        va[k] = __ldg(&a4[addr]);
        vb[k] = __ldg(&b4[addr]);
    }

    float acc = 0.0f;
    #pragma unroll
    for (int k = 0; k < 2; k++) {
        float e0 = va[k].x - vb[k].x;
        float e1 = va[k].y - vb[k].y;
        float e2 = va[k].z - vb[k].z;
        float e3 = va[k].w - vb[k].w;
        acc = fmaf(e0, e0, acc);
        acc = fmaf(e1, e1, acc);
        acc = fmaf(e2, e2, acc);
        acc = fmaf(e3, e3, acc);
    }

    // block reduce (fixed order -> deterministic)
    #pragma unroll
    for (int o = 16; o > 0; o >>= 1)
        acc += __shfl_down_sync(0xffffffffu, acc, o);

    __shared__ float sh[NTHR / 32];
    if ((threadIdx.x & 31) == 0) sh[threadIdx.x >> 5] = acc;
    __syncthreads();

    if (threadIdx.x >= 32) return;             // warp 0 only

    float v = (threadIdx.x < NTHR / 32) ? sh[threadIdx.x] : 0.0f;
    #pragma unroll
    for (int o = 4; o > 0; o >>= 1)            // 8 lanes carry data
        v += __shfl_down_sync(0xffffffffu, v, o);

    if (threadIdx.x != 0) return;

    // deterministic fixed-point accumulate + ticket, fused in one atomic
    unsigned long long fixed =
        __double2ull_rn((double)v * FIX_SCALE);         // v >= 0
    unsigned long long packed = (fixed << 16) | 1ull;
    unsigned long long old = atomicAdd(&g_acc, packed);

    if ((old & 0xFFFFull) == (unsigned long long)(NBLK - 1)) {
        unsigned long long total = (old >> 16) + fixed;
        out[0] = (float)((double)total / (FIX_SCALE * COUNT_));
        g_acc = 0ull;                           // reset for next replay
    }
}

extern "C" void kernel_launch(void* const* d_in, const int* in_sizes, int n_in,
                              void* d_out, int out_size)
{
    const float* yt = (const float*)d_in[0];   // true_frames
    const float* yp = (const float*)d_in[1];   // predicted_frames
    spline_mse_r5<<<NBLK, NTHR>>>(yt, yp, (float*)d_out);
}